// round 12
// baseline (speedup 1.0000x reference)
#include <cuda_runtime.h>
#include <cuda_bf16.h>
#include <cstdint>

#define N_NODES 100000
#define N_EDGES 1600000
#define DIM 128
#define BUCKET_CAP 128   // max degree supported; Binomial(1.6M,1e-5) tail ~1e-80

// ---------------- device scratch (no allocs allowed) ----------------
__device__ __align__(16) float g_agg[(size_t)N_NODES * DIM];      // 51.2 MB
__device__ int   g_cnt[N_NODES];                                  // bucket cursors
__device__ int2  g_edge[(size_t)N_NODES * BUCKET_CAP];            // 102.4 MB buckets
// Quad-packed tf32 W fragments: quad(n, ks, tg) = {bb(k), bb(k+4), bs(k), bs(k+4)},
// k = ks*8 + tg.  Layout: [n][ks*4 + tg] -> 128 x 64 quads.
__device__ uint4 g_Wq[DIM * 64];

// ---------------------------------------------------------------------------
// Init: zero cursors + build quad-packed tf32 split of W (one launch).
// ---------------------------------------------------------------------------
__device__ __forceinline__ uint32_t f2tf32(float f) {
    uint32_t r;
    asm("cvt.rna.tf32.f32 %0, %1;" : "=r"(r) : "f"(f));
    return r;
}

__global__ void init_kernel(const float* __restrict__ W) {
    int i = blockIdx.x * blockDim.x + threadIdx.x;
    if (i < N_NODES) g_cnt[i] = 0;
    if (i < DIM * 64) {
        int n  = i >> 6;
        int r  = i & 63;
        int ks = r >> 2;
        int tg = r & 3;
        int k  = ks * 8 + tg;
        float f0 = __ldg(W + n * DIM + k);
        float f1 = __ldg(W + n * DIM + k + 4);
        uint4 q;
        q.x = f2tf32(f0);                              // bb0
        q.y = f2tf32(f1);                              // bb1
        q.z = f2tf32(f0 - __uint_as_float(q.x));       // bs0
        q.w = f2tf32(f1 - __uint_as_float(q.y));       // bs1
        g_Wq[i] = q;
    }
}

// ---------------------------------------------------------------------------
// Bucket scatter (R11 proven): fixed-capacity per-node buckets.
// ---------------------------------------------------------------------------
__global__ void scatter_kernel(const float* __restrict__ vals,
                               const int* __restrict__ src,
                               const int* __restrict__ dst) {
    int e = blockIdx.x * blockDim.x + threadIdx.x;
    if (e >= N_EDGES) return;
    int d = __ldg(dst + e);
    int pos = atomicAdd(&g_cnt[d], 1);
    if (pos < BUCKET_CAP) {
        int2 p;
        p.x = __ldg(src + e);
        p.y = __float_as_int(__ldg(vals + e));
        g_edge[(size_t)d * BUCKET_CAP + pos] = p;
    }
}

// ---------------------------------------------------------------------------
// Per-node reduce (R4/R8 proven): warp per node, MLP=4 gathers in flight.
// ---------------------------------------------------------------------------
__global__ __launch_bounds__(256) void reduce_kernel(const float* __restrict__ x) {
    const int n    = blockIdx.x * 8 + (threadIdx.x >> 5);
    const int lane = threadIdx.x & 31;
    if (n >= N_NODES) return;

    const int2* seg = g_edge + (size_t)n * BUCKET_CAP;
    int cnt = g_cnt[n];
    if (cnt > BUCKET_CAP) cnt = BUCKET_CAP;
    int e = 0;

    float4 acc = make_float4(0.f, 0.f, 0.f, 0.f);
    for (; e + 3 < cnt; e += 4) {
        int2 p0 = __ldg(seg + e);
        int2 p1 = __ldg(seg + e + 1);
        int2 p2 = __ldg(seg + e + 2);
        int2 p3 = __ldg(seg + e + 3);
        float4 h0 = *reinterpret_cast<const float4*>(x + (long)p0.x * DIM + lane * 4);
        float4 h1 = *reinterpret_cast<const float4*>(x + (long)p1.x * DIM + lane * 4);
        float4 h2 = *reinterpret_cast<const float4*>(x + (long)p2.x * DIM + lane * 4);
        float4 h3 = *reinterpret_cast<const float4*>(x + (long)p3.x * DIM + lane * 4);
        float v0 = __int_as_float(p0.y), v1 = __int_as_float(p1.y);
        float v2 = __int_as_float(p2.y), v3 = __int_as_float(p3.y);
        acc.x += v0 * h0.x + v1 * h1.x + v2 * h2.x + v3 * h3.x;
        acc.y += v0 * h0.y + v1 * h1.y + v2 * h2.y + v3 * h3.y;
        acc.z += v0 * h0.z + v1 * h1.z + v2 * h2.z + v3 * h3.z;
        acc.w += v0 * h0.w + v1 * h1.w + v2 * h2.w + v3 * h3.w;
    }
    for (; e < cnt; e++) {
        int2 p0 = __ldg(seg + e);
        float4 h0 = *reinterpret_cast<const float4*>(x + (long)p0.x * DIM + lane * 4);
        float v0 = __int_as_float(p0.y);
        acc.x += v0 * h0.x;
        acc.y += v0 * h0.y;
        acc.z += v0 * h0.z;
        acc.w += v0 * h0.w;
    }
    *reinterpret_cast<float4*>(g_agg + (long)n * DIM + lane * 4) = acc;
}

// ---------------------------------------------------------------------------
// TF32 tensor GEMM, 3xTF32, quad-packed B, warp tile 32 rows x 64 cols:
//   out[m][n] = sum_k agg[m][k] * W[n][k];  D += Ab*Wb + Ab*Ws + As*Wb
// Block: 512 threads (16 warps), 256 rows x 128 cols.
//   warp w: row-group (w>>1)*32, col-group (w&1)*64 (8 n-tiles).
// Shared: quad array [128][68] (pitch 68 quads -> conflict-free LDS.128:
//   per 8-lane phase quad-bank = (4g+tg)%8, all distinct).
// Inner loop per (ks, nt): 1 LDS.128 + 6 MMA (2 m-tiles x 3 splits).
// ---------------------------------------------------------------------------
__device__ __forceinline__ void mma_tf32(float* d, const uint32_t* a,
                                         uint32_t b0, uint32_t b1) {
    asm("mma.sync.aligned.m16n8k8.row.col.f32.tf32.tf32.f32 "
        "{%0,%1,%2,%3}, {%4,%5,%6,%7}, {%8,%9}, {%0,%1,%2,%3};"
        : "+f"(d[0]), "+f"(d[1]), "+f"(d[2]), "+f"(d[3])
        : "r"(a[0]), "r"(a[1]), "r"(a[2]), "r"(a[3]), "r"(b0), "r"(b1));
}

#define WQ_PITCH 68                        // quads per row (68 % 8 == 4)
#define SMEM_GEMM (DIM * WQ_PITCH * 16)    // 139,264 B
#define GEMM_THREADS 512
#define ROWS_PER_BLK 256

__global__ __launch_bounds__(GEMM_THREADS) void mma_gemm_kernel(float* __restrict__ out) {
    extern __shared__ uint4 wq_s[];        // [128][WQ_PITCH]

    const int tid  = threadIdx.x;
    const int lane = tid & 31;
    const int wid  = tid >> 5;     // 0..15
    const int g    = lane >> 2;    // row within fragment
    const int tg   = lane & 3;     // col within fragment
    const int rg   = wid >> 1;     // row group 0..7 (32 rows each)
    const int cg   = wid & 1;      // col group 0..1 (64 cols each)

    // Stage quad-packed W: 8192 quads, 16 per thread; conflict-free writes.
    for (int idx = tid; idx < DIM * 64; idx += GEMM_THREADS) {
        int row = idx >> 6;
        int q   = idx & 63;
        wq_s[row * WQ_PITCH + q] = g_Wq[idx];
    }
    __syncthreads();

    const long row0 = (long)blockIdx.x * ROWS_PER_BLK + rg * 32;
    // m-tile 0 rows: row0+g, row0+g+8 ; m-tile 1 rows: +16, +24
    long rr[4];
    bool ok[4];
#pragma unroll
    for (int i = 0; i < 4; i++) {
        rr[i] = row0 + g + i * 8;
        ok[i] = rr[i] < N_NODES;
    }
    const float* ap[4];
#pragma unroll
    for (int i = 0; i < 4; i++) ap[i] = g_agg + (ok[i] ? rr[i] : 0) * DIM;

    float acc[2][8][4];
#pragma unroll
    for (int m = 0; m < 2; m++)
#pragma unroll
        for (int nt = 0; nt < 8; nt++)
#pragma unroll
            for (int j = 0; j < 4; j++) acc[m][nt][j] = 0.f;

    const uint4* wq_col = wq_s + (size_t)(cg * 64) * WQ_PITCH;

#pragma unroll 1
    for (int ks = 0; ks < 16; ks++) {
        // A fragments for both m-tiles (f32 -> tf32 big/small)
        float af[2][4];
        af[0][0] = ok[0] ? __ldg(ap[0] + ks * 8 + tg)     : 0.f;
        af[0][1] = ok[1] ? __ldg(ap[1] + ks * 8 + tg)     : 0.f;
        af[0][2] = ok[0] ? __ldg(ap[0] + ks * 8 + tg + 4) : 0.f;
        af[0][3] = ok[1] ? __ldg(ap[1] + ks * 8 + tg + 4) : 0.f;
        af[1][0] = ok[2] ? __ldg(ap[2] + ks * 8 + tg)     : 0.f;
        af[1][1] = ok[3] ? __ldg(ap[3] + ks * 8 + tg)     : 0.f;
        af[1][2] = ok[2] ? __ldg(ap[2] + ks * 8 + tg + 4) : 0.f;
        af[1][3] = ok[3] ? __ldg(ap[3] + ks * 8 + tg + 4) : 0.f;

        uint32_t ab[2][4], as[2][4];
#pragma unroll
        for (int m = 0; m < 2; m++)
#pragma unroll
            for (int i = 0; i < 4; i++) {
                ab[m][i] = f2tf32(af[m][i]);
                as[m][i] = f2tf32(af[m][i] - __uint_as_float(ab[m][i]));
            }

#pragma unroll
        for (int nt = 0; nt < 8; nt++) {
            uint4 q = wq_col[(nt * 8 + g) * WQ_PITCH + ks * 4 + tg];
#pragma unroll
            for (int m = 0; m < 2; m++) {
                mma_tf32(acc[m][nt], ab[m], q.x, q.y);  // big*big
                mma_tf32(acc[m][nt], ab[m], q.z, q.w);  // big*small
                mma_tf32(acc[m][nt], as[m], q.x, q.y);  // small*big
            }
        }
    }

    // Epilogue: c0/c1 -> row (g + m*16), cols cg*64 + nt*8 + 2tg;
    //           c2/c3 -> row (g + 8 + m*16).
#pragma unroll
    for (int m = 0; m < 2; m++) {
#pragma unroll
        for (int nt = 0; nt < 8; nt++) {
            int coln = cg * 64 + nt * 8 + tg * 2;
            if (ok[2 * m]) {
                float* op = out + rr[2 * m] * DIM + coln;
                op[0] = acc[m][nt][0];
                op[1] = acc[m][nt][1];
            }
            if (ok[2 * m + 1]) {
                float* op = out + rr[2 * m + 1] * DIM + coln;
                op[0] = acc[m][nt][2];
                op[1] = acc[m][nt][3];
            }
        }
    }
}

// ---------------------------------------------------------------------------
// Launch. Inputs: x, W, vals, src, dst. Output float32 [N_NODES, DIM].
// out = segment_sum(vals * x[src], dst) @ W^T
// ---------------------------------------------------------------------------
extern "C" void kernel_launch(void* const* d_in, const int* in_sizes, int n_in,
                              void* d_out, int out_size) {
    const float* x    = (const float*)d_in[0];
    const float* W    = (const float*)d_in[1];
    const float* vals = (const float*)d_in[2];
    const int*   src  = (const int*)d_in[3];
    const int*   dst  = (const int*)d_in[4];
    float*       out  = (float*)d_out;

    cudaFuncSetAttribute(mma_gemm_kernel, cudaFuncAttributeMaxDynamicSharedMemorySize,
                         SMEM_GEMM);

    init_kernel<<<(N_NODES + 255) / 256, 256>>>(W);
    scatter_kernel<<<(N_EDGES + 255) / 256, 256>>>(vals, src, dst);
    reduce_kernel<<<(N_NODES + 7) / 8, 256>>>(x);
    mma_gemm_kernel<<<(N_NODES + ROWS_PER_BLK - 1) / ROWS_PER_BLK, GEMM_THREADS,
                      SMEM_GEMM>>>(out);
}